// round 16
// baseline (speedup 1.0000x reference)
#include <cuda_runtime.h>

#define BB 32
#define CC 256
#define NN 1024          // H*W
#define MM 32            // grid nodes
#define SEGS 29          // usable intervals = MM-3
#define KSPLIT 16
#define KSL (NN/KSPLIT)  // 64 j per block
#define KCH 32           // j chunk
#define GST 34           // Gs row stride
#define XST 258          // Xs row stride

// ---------------- scratch (device globals; no allocation) ----------------
__device__ float g_a[BB*NN];
__device__ float g_k[BB*NN];
__device__ unsigned g_mm[BB*2];                       // encoded min/max of a per batch
// partial tables, m-interleaved layout: [b][ks][mp=16][c=256][e=2]
__device__ __align__(16) float g_Sp[BB*KSPLIT*MM*CC];
__device__ float g_Zp[BB*KSPLIT*MM];
// reduced table (same m-interleaved layout per batch: [mp][c][e]) + Z
__device__ __align__(16) float g_S[BB*MM*CC];
__device__ float g_Z[BB*MM];

// order-preserving float<->uint encoding for atomicMin/Max
static __device__ __forceinline__ unsigned enc_f(float f){
    unsigned b = __float_as_uint(f);
    return (b & 0x80000000u) ? ~b : (b | 0x80000000u);
}
static __device__ __forceinline__ float dec_f(unsigned e){
    unsigned b = (e & 0x80000000u) ? (e ^ 0x80000000u) : ~e;
    return __uint_as_float(b);
}
// identical expression in k2 and k3 -> identical IEEE results
static __device__ __forceinline__ void get_grid(int b, float& lo, float& hs){
    float amin = dec_f(g_mm[2*b]);
    float amax = dec_f(g_mm[2*b+1]);
    lo = amin - 1e-4f;
    float hi = amax + 1e-4f;
    hs = (hi - lo) * (1.0f/(float)SEGS);
}

// ---------------- k0: init min/max ----------------
__global__ void k_init(){
    int tid = threadIdx.x;
    if (tid < BB){ g_mm[2*tid] = 0xFFFFFFFFu; g_mm[2*tid+1] = 0u; }
}

// ---------------- k1: a,k scalars + per-batch min/max(a) ----------------
__global__ void __launch_bounds__(256) k1(const float* __restrict__ h,
                                          const float* __restrict__ w1,
                                          const float* __restrict__ b1,
                                          const float* __restrict__ w2,
                                          const float* __restrict__ b2){
    __shared__ float w1s[CC], w2s[CC];
    __shared__ float smn[8], smx[8];
    int b  = blockIdx.x >> 2;
    int pc = blockIdx.x & 3;
    int tid = threadIdx.x;
    w1s[tid] = w1[tid];
    w2s[tid] = w2[tid];
    __syncthreads();

    int p = pc*256 + tid;
    const float* hp = h + (size_t)b*CC*NN + p;
    float av = b1[0], kv = b2[0];
#pragma unroll 8
    for (int c = 0; c < CC; ++c){
        float x = hp[(size_t)c*NN];
        av = fmaf(x, w1s[c], av);
        kv = fmaf(x, w2s[c], kv);
    }
    g_a[b*NN + p] = av;
    g_k[b*NN + p] = kv;

    float mn = av, mx = av;
#pragma unroll
    for (int o = 16; o; o >>= 1){
        mn = fminf(mn, __shfl_xor_sync(0xFFFFFFFFu, mn, o));
        mx = fmaxf(mx, __shfl_xor_sync(0xFFFFFFFFu, mx, o));
    }
    int w = tid >> 5;
    if ((tid & 31) == 0){ smn[w] = mn; smx[w] = mx; }
    __syncthreads();
    if (tid == 0){
#pragma unroll
        for (int i = 1; i < 8; ++i){ mn = fminf(mn, smn[i]); mx = fmaxf(mx, smx[i]); }
        atomicMin(&g_mm[2*b],   enc_f(mn));
        atomicMax(&g_mm[2*b+1], enc_f(mx));
    }
}

// ---------------- k2: partial table matmul, no atomics ----------------
// grid (32, 16) = (batch, K-split of 64 j); 128 threads = 4 warps.
// Warp w owns m in [8w, 8w+8); each thread owns 8 c's {2cp,2cp+1 : cp=lane+32q}.
__global__ void __launch_bounds__(128) k2(const float* __restrict__ h){
    __shared__ __align__(16) float Gs[KCH*GST];   // [jj][m] non-duplicated
    __shared__ __align__(16) float Xs[KCH*XST];   // [jj][c]

    int b   = blockIdx.x;
    int ks  = blockIdx.y;
    int tid = threadIdx.x;
    int warp = tid >> 5;          // 0..3 -> m0 = 8*warp
    int lane = tid & 31;
    int m0   = warp*8;

    float lo, hs; get_grid(b, lo, hs);
    float rmul = __expf(2.0f*hs);
    int j0b = ks*KSL;

    unsigned long long acc[4][8];  // [m-pair][c]
#pragma unroll
    for (int mi = 0; mi < 4; ++mi)
#pragma unroll
        for (int q = 0; q < 8; ++q) acc[mi][q] = 0ull;

    float zacc = 0.f;

    for (int ch = 0; ch < KSL/KCH; ++ch){
        int j0 = j0b + ch*KCH;

        // --- G eval: thread (warp,lane) evals m in [8w,8w+8) for jj=lane ---
        {
            float kv = __ldg(&g_k[b*NN + j0 + lane]);
            float s0 = lo + (float)(m0 - 1)*hs + kv;
            float t  = __expf(2.0f*s0);
#pragma unroll
            for (int i = 0; i < 8; ++i){
                float u = __fdividef(t - 1.0f, t + 1.0f); // tanh
                Gs[lane*GST + m0 + i] = __expf(u);
                t *= rmul;
            }
        }
        // --- X stage: h[b][cc][j0..j0+31] -> Xs[jj][cc] ---
#pragma unroll
        for (int it = 0; it < 16; ++it){
            int idx = it*128 + tid;           // 0..2047
            int cc = idx >> 3, q4 = idx & 7;
            float4 v = *reinterpret_cast<const float4*>(
                &h[((size_t)b*CC + cc)*NN + j0 + q4*4]);
            Xs[(q4*4+0)*XST + cc] = v.x;
            Xs[(q4*4+1)*XST + cc] = v.y;
            Xs[(q4*4+2)*XST + cc] = v.z;
            Xs[(q4*4+3)*XST + cc] = v.w;
        }
        __syncthreads();

        if (tid < 32){                        // warp 0: Z partial
            float zs = 0.f;
#pragma unroll
            for (int jj = 0; jj < KCH; ++jj) zs += Gs[jj*GST + tid];
            zacc += zs;
        }

        // --- inner product: gp = warp-broadcast LDS.64, xp = LDS.64 pairs ---
#pragma unroll 2
        for (int jj = 0; jj < KCH; ++jj){
            unsigned long long gp[4];
#pragma unroll
            for (int mi = 0; mi < 4; ++mi)
                gp[mi] = *reinterpret_cast<const unsigned long long*>(&Gs[jj*GST + m0 + 2*mi]);
#pragma unroll
            for (int q = 0; q < 4; ++q){
                float2 xv = *reinterpret_cast<const float2*>(&Xs[jj*XST + 2*(lane + 32*q)]);
                unsigned long long xe, xo;
                asm("mov.b64 %0, {%1,%1};" : "=l"(xe) : "f"(xv.x));
                asm("mov.b64 %0, {%1,%1};" : "=l"(xo) : "f"(xv.y));
#pragma unroll
                for (int mi = 0; mi < 4; ++mi){
                    asm("fma.rn.f32x2 %0, %1, %2, %0;" : "+l"(acc[mi][2*q  ]) : "l"(gp[mi]), "l"(xe));
                    asm("fma.rn.f32x2 %0, %1, %2, %0;" : "+l"(acc[mi][2*q+1]) : "l"(gp[mi]), "l"(xo));
                }
            }
        }
        __syncthreads();
    }

    // --- writeback: STG.128 to interleaved partials [b][ks][mp][c][e] ---
    float4* Sp4 = reinterpret_cast<float4*>(g_Sp) + ((size_t)(b*KSPLIT + ks))*2048;
#pragma unroll
    for (int mi = 0; mi < 4; ++mi){
        int mp = warp*4 + mi;
#pragma unroll
        for (int q = 0; q < 4; ++q){
            int cp = lane + 32*q;
            float4 v;
            asm("mov.b64 {%0,%1}, %2;" : "=f"(v.x), "=f"(v.y) : "l"(acc[mi][2*q]));
            asm("mov.b64 {%0,%1}, %2;" : "=f"(v.z), "=f"(v.w) : "l"(acc[mi][2*q+1]));
            Sp4[mp*128 + cp] = v;
        }
    }
    if (tid < 32) g_Zp[(b*KSPLIT + ks)*MM + tid] = zacc;
}

// ---------------- k2r: reduce partials (pure float4 sums) ----------------
__global__ void __launch_bounds__(256) k2r(){
    const float4* Sp4 = reinterpret_cast<const float4*>(g_Sp);
    float4* S4 = reinterpret_cast<float4*>(g_S);
    int tid = threadIdx.x;
#pragma unroll
    for (int i = 0; i < 4; ++i){
        int F = i*16384 + blockIdx.x*256 + tid;   // 0..65535
        int b = F >> 11, g = F & 2047;
        float4 s = make_float4(0.f,0.f,0.f,0.f);
#pragma unroll
        for (int ksv = 0; ksv < KSPLIT; ++ksv){
            float4 v = Sp4[(size_t)(b*KSPLIT + ksv)*2048 + g];
            s.x += v.x; s.y += v.y; s.z += v.z; s.w += v.w;
        }
        S4[F] = s;
    }
    if (blockIdx.x < 4){
        int zi = blockIdx.x*256 + tid;            // 0..1023
        int b = zi >> 5, m = zi & 31;
        float z = 0.f;
#pragma unroll
        for (int ksv = 0; ksv < KSPLIT; ++ksv)
            z += g_Zp[(b*KSPLIT + ksv)*MM + m];
        g_Z[zi] = z;
    }
}

// ---------------- k3: smem table (c-quarter) + cubic interpolate + LeakyReLU ----------------
// grid (32, 16): y = pc (4) x cq (4); 256 threads
__global__ void __launch_bounds__(256) k3(float* __restrict__ out){
    __shared__ float Ss[MM*65];   // bank = (seg + c) mod 32 -> conflict-free gather
    __shared__ float Zs[MM];

    int b  = blockIdx.x;
    int pc = blockIdx.y & 3;
    int cq = blockIdx.y >> 2;
    int tid = threadIdx.x;

    // de-interleave this batch's c-quarter table into smem
    const float4* S4 = reinterpret_cast<const float4*>(g_S) + (size_t)b*2048;
#pragma unroll
    for (int it = 0; it < 2; ++it){
        int id = it*256 + tid;            // 0..511
        int mp = id >> 5, t = id & 31;
        float4 v = __ldg(&S4[mp*128 + 32*cq + t]);
        Ss[(2*mp  )*65 + 2*t  ] = v.x;
        Ss[(2*mp+1)*65 + 2*t  ] = v.y;
        Ss[(2*mp  )*65 + 2*t+1] = v.z;
        Ss[(2*mp+1)*65 + 2*t+1] = v.w;
    }
    if (tid < MM) Zs[tid] = g_Z[b*MM + tid];
    __syncthreads();

    int p = pc*256 + tid;
    float lo, hs; get_grid(b, lo, hs);
    float a = g_a[b*NN + p];
    float u = (a - lo) / hs;
    int seg = (int)floorf(u);
    seg = max(0, min(SEGS-1, seg));
    float s = u - (float)seg;

    // Lagrange weights for nodes at offsets {-1,0,1,2}
    float w0 = -s*(s-1.f)*(s-2.f)*(1.f/6.f);
    float w1 = (s*s-1.f)*(s-2.f)*0.5f;
    float w2 = -s*(s+1.f)*(s-2.f)*0.5f;
    float w3 = s*(s*s-1.f)*(1.f/6.f);

    float z  = w0*Zs[seg] + w1*Zs[seg+1] + w2*Zs[seg+2] + w3*Zs[seg+3];
    float rz = 1.0f / z;

    const float* S0 = &Ss[seg*65];
    float* op = out + (size_t)b*CC*NN + (size_t)(cq*64)*NN + p;

#pragma unroll 8
    for (int c = 0; c < 64; ++c){
        float v = w0*S0[c] + w1*S0[c+65] + w2*S0[c+130] + w3*S0[c+195];
        v *= rz;
        v = (v >= 0.f) ? v : 0.2f*v;
        op[(size_t)c*NN] = v;
    }
}

// ---------------- entry ----------------
extern "C" void kernel_launch(void* const* d_in, const int* in_sizes, int n_in,
                              void* d_out, int out_size){
    (void)in_sizes; (void)n_in; (void)out_size;
    const float* h  = (const float*)d_in[0];
    const float* w1 = (const float*)d_in[1];
    const float* b1 = (const float*)d_in[2];
    const float* w2 = (const float*)d_in[3];
    const float* b2 = (const float*)d_in[4];
    float* out = (float*)d_out;

    k_init<<<1, 64>>>();
    k1<<<128, 256>>>(h, w1, b1, w2, b2);
    k2<<<dim3(32, KSPLIT), 128>>>(h);
    k2r<<<64, 256>>>();
    k3<<<dim3(32, 16), 256>>>(out);
}

// round 17
// speedup vs baseline: 1.1209x; 1.1209x over previous
#include <cuda_runtime.h>

#define BB 32
#define CC 256
#define NN 1024          // H*W
#define MM 32            // grid nodes
#define SEGS 29          // usable intervals = MM-3
#define KSPLIT 16
#define KSL (NN/KSPLIT)  // 64 j per block
#define KCH 32           // j chunk
#define GST 34           // Gs row stride
#define XST 258          // Xs row stride

// ---------------- scratch (device globals; zero-initialized, no allocation) ----------------
__device__ float g_a[BB*NN];
__device__ float g_k[BB*NN];
__device__ unsigned g_mm[BB*2];        // [2b]=max(enc(-a)) -> min, [2b+1]=max(enc(a)); identity 0
__device__ float2 g_grid[BB];          // snapshot {lo, hs} taken by k2r
// partial tables, m-interleaved layout: [b][ks][mp=16][c=256][e=2]
__device__ __align__(16) float g_Sp[BB*KSPLIT*MM*CC];
__device__ float g_Zp[BB*KSPLIT*MM];
// reduced table (m-interleaved per batch: [mp][c][e]) + Z
__device__ __align__(16) float g_S[BB*MM*CC];
__device__ float g_Z[BB*MM];

// order-preserving float<->uint encoding (monotone increasing)
static __device__ __forceinline__ unsigned enc_f(float f){
    unsigned b = __float_as_uint(f);
    return (b & 0x80000000u) ? ~b : (b | 0x80000000u);
}
static __device__ __forceinline__ float dec_f(unsigned e){
    unsigned b = (e & 0x80000000u) ? (e ^ 0x80000000u) : ~e;
    return __uint_as_float(b);
}
// identical expression in k2 and k2r -> identical IEEE bits
static __device__ __forceinline__ void get_grid(int b, float& lo, float& hs){
    float amin = -dec_f(g_mm[2*b]);        // stored as max(enc(-a))
    float amax =  dec_f(g_mm[2*b+1]);
    lo = amin - 1e-4f;
    float hi = amax + 1e-4f;
    hs = (hi - lo) * (1.0f/(float)SEGS);
}

// ---------------- k1: a,k scalars + per-batch min/max(a) ----------------
__global__ void __launch_bounds__(256) k1(const float* __restrict__ h,
                                          const float* __restrict__ w1,
                                          const float* __restrict__ b1,
                                          const float* __restrict__ w2,
                                          const float* __restrict__ b2){
    __shared__ float w1s[CC], w2s[CC];
    __shared__ float smn[8], smx[8];
    int b  = blockIdx.x >> 2;
    int pc = blockIdx.x & 3;
    int tid = threadIdx.x;
    w1s[tid] = w1[tid];
    w2s[tid] = w2[tid];
    __syncthreads();

    int p = pc*256 + tid;
    const float* hp = h + (size_t)b*CC*NN + p;
    float av = b1[0], kv = b2[0];
#pragma unroll 8
    for (int c = 0; c < CC; ++c){
        float x = hp[(size_t)c*NN];
        av = fmaf(x, w1s[c], av);
        kv = fmaf(x, w2s[c], kv);
    }
    g_a[b*NN + p] = av;
    g_k[b*NN + p] = kv;

    float mn = av, mx = av;
#pragma unroll
    for (int o = 16; o; o >>= 1){
        mn = fminf(mn, __shfl_xor_sync(0xFFFFFFFFu, mn, o));
        mx = fmaxf(mx, __shfl_xor_sync(0xFFFFFFFFu, mx, o));
    }
    int w = tid >> 5;
    if ((tid & 31) == 0){ smn[w] = mn; smx[w] = mx; }
    __syncthreads();
    if (tid == 0){
#pragma unroll
        for (int i = 1; i < 8; ++i){ mn = fminf(mn, smn[i]); mx = fmaxf(mx, smx[i]); }
        atomicMax(&g_mm[2*b],   enc_f(-mn));   // min via max of negated
        atomicMax(&g_mm[2*b+1], enc_f(mx));
    }
}

// ---------------- k2: partial table matmul, no atomics ----------------
// grid (32, 16) = (batch, K-split of 64 j); 128 threads = 4 warps.
// Warp w owns m in [8w, 8w+8); each thread owns 8 c's {2cp,2cp+1 : cp=lane+32q}.
__global__ void __launch_bounds__(128) k2(const float* __restrict__ h){
    __shared__ __align__(16) float Gs[KCH*GST];   // [jj][m] non-duplicated
    __shared__ __align__(16) float Xs[KCH*XST];   // [jj][c]

    int b   = blockIdx.x;
    int ks  = blockIdx.y;
    int tid = threadIdx.x;
    int warp = tid >> 5;          // 0..3 -> m0 = 8*warp
    int lane = tid & 31;
    int m0   = warp*8;

    float lo, hs; get_grid(b, lo, hs);
    float rmul = __expf(2.0f*hs);
    int j0b = ks*KSL;

    unsigned long long acc[4][8];  // [m-pair][c]
#pragma unroll
    for (int mi = 0; mi < 4; ++mi)
#pragma unroll
        for (int q = 0; q < 8; ++q) acc[mi][q] = 0ull;

    float zacc = 0.f;

    for (int ch = 0; ch < KSL/KCH; ++ch){
        int j0 = j0b + ch*KCH;

        // --- G eval: thread (warp,lane) evals m in [8w,8w+8) for jj=lane ---
        {
            float kv = __ldg(&g_k[b*NN + j0 + lane]);
            float s0 = lo + (float)(m0 - 1)*hs + kv;
            float t  = __expf(2.0f*s0);
#pragma unroll
            for (int i = 0; i < 8; ++i){
                float u = __fdividef(t - 1.0f, t + 1.0f); // tanh
                Gs[lane*GST + m0 + i] = __expf(u);
                t *= rmul;
            }
        }
        // --- X stage: h[b][cc][j0..j0+31] -> Xs[jj][cc] ---
#pragma unroll
        for (int it = 0; it < 16; ++it){
            int idx = it*128 + tid;           // 0..2047
            int cc = idx >> 3, q4 = idx & 7;
            float4 v = *reinterpret_cast<const float4*>(
                &h[((size_t)b*CC + cc)*NN + j0 + q4*4]);
            Xs[(q4*4+0)*XST + cc] = v.x;
            Xs[(q4*4+1)*XST + cc] = v.y;
            Xs[(q4*4+2)*XST + cc] = v.z;
            Xs[(q4*4+3)*XST + cc] = v.w;
        }
        __syncthreads();

        if (tid < 32){                        // warp 0: Z partial
            float zs = 0.f;
#pragma unroll
            for (int jj = 0; jj < KCH; ++jj) zs += Gs[jj*GST + tid];
            zacc += zs;
        }

        // --- inner product: gp = warp-broadcast LDS.64, xp = LDS.64 pairs ---
#pragma unroll 2
        for (int jj = 0; jj < KCH; ++jj){
            unsigned long long gp[4];
#pragma unroll
            for (int mi = 0; mi < 4; ++mi)
                gp[mi] = *reinterpret_cast<const unsigned long long*>(&Gs[jj*GST + m0 + 2*mi]);
#pragma unroll
            for (int q = 0; q < 4; ++q){
                float2 xv = *reinterpret_cast<const float2*>(&Xs[jj*XST + 2*(lane + 32*q)]);
                unsigned long long xe, xo;
                asm("mov.b64 %0, {%1,%1};" : "=l"(xe) : "f"(xv.x));
                asm("mov.b64 %0, {%1,%1};" : "=l"(xo) : "f"(xv.y));
#pragma unroll
                for (int mi = 0; mi < 4; ++mi){
                    asm("fma.rn.f32x2 %0, %1, %2, %0;" : "+l"(acc[mi][2*q  ]) : "l"(gp[mi]), "l"(xe));
                    asm("fma.rn.f32x2 %0, %1, %2, %0;" : "+l"(acc[mi][2*q+1]) : "l"(gp[mi]), "l"(xo));
                }
            }
        }
        __syncthreads();
    }

    // --- writeback: STG.128 to interleaved partials [b][ks][mp][c][e] ---
    float4* Sp4 = reinterpret_cast<float4*>(g_Sp) + ((size_t)(b*KSPLIT + ks))*2048;
#pragma unroll
    for (int mi = 0; mi < 4; ++mi){
        int mp = warp*4 + mi;
#pragma unroll
        for (int q = 0; q < 4; ++q){
            int cp = lane + 32*q;
            float4 v;
            asm("mov.b64 {%0,%1}, %2;" : "=f"(v.x), "=f"(v.y) : "l"(acc[mi][2*q]));
            asm("mov.b64 {%0,%1}, %2;" : "=f"(v.z), "=f"(v.w) : "l"(acc[mi][2*q+1]));
            Sp4[mp*128 + cp] = v;
        }
    }
    if (tid < 32) g_Zp[(b*KSPLIT + ks)*MM + tid] = zacc;
}

// ---------------- k2r: wide reduce (1 float4 out / thread, MLP=16) + grid snapshot ----------------
__global__ void __launch_bounds__(128) k2r(){
    const float4* Sp4 = reinterpret_cast<const float4*>(g_Sp);
    float4* S4 = reinterpret_cast<float4*>(g_S);
    int F = blockIdx.x*128 + threadIdx.x;     // 0..65535
    int b = F >> 11, g = F & 2047;

    float4 v[KSPLIT];
#pragma unroll
    for (int ksv = 0; ksv < KSPLIT; ++ksv)
        v[ksv] = Sp4[(size_t)(b*KSPLIT + ksv)*2048 + g];
    float4 s = make_float4(0.f,0.f,0.f,0.f);
#pragma unroll
    for (int ksv = 0; ksv < KSPLIT; ++ksv){
        s.x += v[ksv].x; s.y += v[ksv].y; s.z += v[ksv].z; s.w += v[ksv].w;
    }
    S4[F] = s;

    if (blockIdx.x < 8){
        int zi = blockIdx.x*128 + threadIdx.x;   // 0..1023
        int zb = zi >> 5, m = zi & 31;
        float z = 0.f;
#pragma unroll
        for (int ksv = 0; ksv < KSPLIT; ++ksv)
            z += g_Zp[(zb*KSPLIT + ksv)*MM + m];
        g_Z[zi] = z;
    }

    // snapshot grid params (bit-identical to k2's), then reset g_mm for next replay
    if (F < BB){
        float lo, hsv; get_grid(F, lo, hsv);
        g_grid[F] = make_float2(lo, hsv);
        g_mm[2*F] = 0u; g_mm[2*F+1] = 0u;
    }
}

// ---------------- k3: smem table (c-quarter) + cubic interpolate + LeakyReLU ----------------
// grid (32, 16): y = pc (4) x cq (4); 256 threads
__global__ void __launch_bounds__(256) k3(float* __restrict__ out){
    __shared__ float Ss[MM*65];   // bank = (seg + c) mod 32 -> conflict-free gather
    __shared__ float Zs[MM];

    int b  = blockIdx.x;
    int pc = blockIdx.y & 3;
    int cq = blockIdx.y >> 2;
    int tid = threadIdx.x;

    // de-interleave this batch's c-quarter table into smem
    const float4* S4 = reinterpret_cast<const float4*>(g_S) + (size_t)b*2048;
#pragma unroll
    for (int it = 0; it < 2; ++it){
        int id = it*256 + tid;            // 0..511
        int mp = id >> 5, t = id & 31;
        float4 v = __ldg(&S4[mp*128 + 32*cq + t]);
        Ss[(2*mp  )*65 + 2*t  ] = v.x;
        Ss[(2*mp+1)*65 + 2*t  ] = v.y;
        Ss[(2*mp  )*65 + 2*t+1] = v.z;
        Ss[(2*mp+1)*65 + 2*t+1] = v.w;
    }
    if (tid < MM) Zs[tid] = g_Z[b*MM + tid];
    __syncthreads();

    int p = pc*256 + tid;
    float2 gr = g_grid[b];
    float lo = gr.x, hs = gr.y;
    float a = g_a[b*NN + p];
    float u = (a - lo) / hs;
    int seg = (int)floorf(u);
    seg = max(0, min(SEGS-1, seg));
    float s = u - (float)seg;

    // Lagrange weights for nodes at offsets {-1,0,1,2}
    float w0 = -s*(s-1.f)*(s-2.f)*(1.f/6.f);
    float w1 = (s*s-1.f)*(s-2.f)*0.5f;
    float w2 = -s*(s+1.f)*(s-2.f)*0.5f;
    float w3 = s*(s*s-1.f)*(1.f/6.f);

    float z  = w0*Zs[seg] + w1*Zs[seg+1] + w2*Zs[seg+2] + w3*Zs[seg+3];
    float rz = 1.0f / z;

    const float* S0 = &Ss[seg*65];
    float* op = out + (size_t)b*CC*NN + (size_t)(cq*64)*NN + p;

#pragma unroll 8
    for (int c = 0; c < 64; ++c){
        float v = w0*S0[c] + w1*S0[c+65] + w2*S0[c+130] + w3*S0[c+195];
        v *= rz;
        v = (v >= 0.f) ? v : 0.2f*v;
        op[(size_t)c*NN] = v;
    }
}

// ---------------- entry ----------------
extern "C" void kernel_launch(void* const* d_in, const int* in_sizes, int n_in,
                              void* d_out, int out_size){
    (void)in_sizes; (void)n_in; (void)out_size;
    const float* h  = (const float*)d_in[0];
    const float* w1 = (const float*)d_in[1];
    const float* b1 = (const float*)d_in[2];
    const float* w2 = (const float*)d_in[3];
    const float* b2 = (const float*)d_in[4];
    float* out = (float*)d_out;

    k1<<<128, 256>>>(h, w1, b1, w2, b2);
    k2<<<dim3(32, KSPLIT), 128>>>(h);
    k2r<<<512, 128>>>();
    k3<<<dim3(32, 16), 256>>>(out);
}